// round 10
// baseline (speedup 1.0000x reference)
#include <cuda_runtime.h>
#include <cuda_fp16.h>
#include <cstdint>

#define BB 2
#define NN 8192
#define CC 256
#define KK 40
#define MM (BB * NN)

// ================= scratch =================
__device__ float g_q[MM * CC];
__device__ float g_k[MM * CC];
__device__ float g_v[MM * CC];
__device__ float g_part[BB * 32 * CC];
__device__ float g_u[BB * CC];
__device__ float g_score[BB * NN];
__device__ int   g_selidx[BB * KK];
__device__ float g_T[BB * KK * CC];
__device__ float g_T2[BB * KK * CC];
__device__ float g_Pq[MM * KK];

// ================= helpers (family-portable PTX only) =================
__device__ __forceinline__ uint32_t pk2(float lo, float hi) {
    __half2 h = __floats2half2_rn(lo, hi);
    return *reinterpret_cast<uint32_t*>(&h);
}
__device__ __forceinline__ void mma16(float* c, const uint32_t* a, const uint32_t* b) {
    asm volatile(
        "mma.sync.aligned.m16n8k16.row.col.f32.f16.f16.f32 "
        "{%0,%1,%2,%3}, {%4,%5,%6,%7}, {%8,%9}, {%0,%1,%2,%3};"
        : "+f"(c[0]), "+f"(c[1]), "+f"(c[2]), "+f"(c[3])
        : "r"(a[0]), "r"(a[1]), "r"(a[2]), "r"(a[3]), "r"(b[0]), "r"(b[1]));
}

// ================= xsum: per-chunk partial column sums + zero g_T =================
__global__ __launch_bounds__(256) void xsum_kernel(const float* __restrict__ x) {
    __shared__ float4 red[4][64];
    int b = blockIdx.x >> 5, chunk = blockIdx.x & 31;
    int c4 = threadIdx.x & 63, rl = threadIdx.x >> 6;
    const float* base = x + ((size_t)b * NN + chunk * 256 + rl) * CC + c4 * 4;
    float4 s = make_float4(0.f, 0.f, 0.f, 0.f);
#pragma unroll 8
    for (int n = 0; n < 64; n++) {
        float4 v = *(const float4*)(base + (size_t)n * 4 * CC);
        s.x += v.x; s.y += v.y; s.z += v.z; s.w += v.w;
    }
    red[rl][c4] = s;
    for (int i = blockIdx.x * 256 + threadIdx.x; i < BB * KK * CC; i += 64 * 256)
        g_T[i] = 0.f;
    __syncthreads();
    if (rl == 0) {
        float4 a = red[0][c4], b2 = red[1][c4], c2 = red[2][c4], d = red[3][c4];
        float4 o;
        o.x = a.x + b2.x + c2.x + d.x; o.y = a.y + b2.y + c2.y + d.y;
        o.z = a.z + b2.z + c2.z + d.z; o.w = a.w + b2.w + c2.w + d.w;
        *(float4*)&g_part[(size_t)(b * 32 + chunk) * CC + c4 * 4] = o;
    }
}

// qsum = Wq*xsum + N*bq (fp32 exact), then u = Wk^T * qsum
__global__ void prep_kernel(const float* __restrict__ Wq, const float* __restrict__ bq,
                            const float* __restrict__ Wk) {
    __shared__ float xs[CC], qs[CC];
    int b = blockIdx.x, tid = threadIdx.x, w = tid >> 5, lane = tid & 31;
    float sx = 0.f;
#pragma unroll 8
    for (int ch = 0; ch < 32; ch++) sx += g_part[(size_t)(b * 32 + ch) * CC + tid];
    xs[tid] = sx;
    __syncthreads();
    for (int c = w * 32; c < w * 32 + 32; c++) {
        const float* wr = Wq + (size_t)c * CC;
        float s = 0.f;
#pragma unroll
        for (int i = 0; i < 8; i++) s += xs[lane + 32 * i] * wr[lane + 32 * i];
#pragma unroll
        for (int o = 16; o; o >>= 1) s += __shfl_xor_sync(0xFFFFFFFFu, s, o);
        if (lane == 0) qs[c] = s + (float)NN * bq[c];
    }
    __syncthreads();
    int c = tid;
    float u = 0.f;
#pragma unroll 8
    for (int d = 0; d < CC; d++) u += qs[d] * Wk[(size_t)d * CC + c];
    g_u[b * CC + c] = u;
}

// score_m = u_b . x_m  (order-identical to qsum.k_m/16 up to constant; exact fp32)
__global__ void score_kernel(const float* __restrict__ x) {
    int warp = threadIdx.x >> 5, lane = threadIdx.x & 31;
    int row = blockIdx.x * 8 + warp;
    int b = row >> 13;
    const float4* xr = (const float4*)(x + (size_t)row * CC);
    const float4* u = (const float4*)(&g_u[b * CC]);
    float4 v0 = xr[lane], v1 = xr[lane + 32];
    float4 u0 = u[lane], u1 = u[lane + 32];
    float s = v0.x * u0.x + v0.y * u0.y + v0.z * u0.z + v0.w * u0.w
            + v1.x * u1.x + v1.y * u1.y + v1.z * u1.z + v1.w * u1.w;
#pragma unroll
    for (int o = 16; o; o >>= 1) s += __shfl_xor_sync(0xFFFFFFFFu, s, o);
    if (lane == 0) g_score[row] = s;
}

// ================= exact top-40 via radix-256 select (one CTA per batch) =================
__global__ __launch_bounds__(1024) void topk_kernel() {
    __shared__ uint32_t su[NN];
    __shared__ int hist[256];
    __shared__ int c_hi_sh, bin_sh, cnt, chunk_tot, eq_cnt;
    __shared__ int wcnt[32], wpre[32];
    const int b = blockIdx.x, tid = threadIdx.x, lane = tid & 31, wid = tid >> 5;

    for (int i = tid; i < NN; i += 1024) {
        uint32_t u = __float_as_uint(g_score[b * NN + i]);
        su[i] = (u & 0x80000000u) ? ~u : (u | 0x80000000u);
    }
    if (tid == 0) { cnt = 0; eq_cnt = 0; }

    uint32_t prefix = 0;
    int K_rem = KK;
#pragma unroll
    for (int shift = 24; shift >= 0; shift -= 8) {
        __syncthreads();
        if (tid < 256) hist[tid] = 0;
        __syncthreads();
        const uint32_t mask_hi = (shift == 24) ? 0u : (0xFFFFFFFFu << (shift + 8));
#pragma unroll
        for (int c = 0; c < NN / 1024; c++) {
            uint32_t u = su[c * 1024 + tid];
            int bin = ((u & mask_hi) == prefix) ? (int)((u >> shift) & 0xFF) : 256;
            uint32_t grp = __match_any_sync(0xFFFFFFFFu, bin);
            if (bin < 256 && (__ffs(grp) - 1) == lane) atomicAdd(&hist[bin], __popc(grp));
        }
        __syncthreads();
        if (wid == 0) {
            int h[8], lsum = 0;
#pragma unroll
            for (int j = 0; j < 8; j++) { h[j] = hist[lane * 8 + j]; lsum += h[j]; }
            int acc = lsum;
#pragma unroll
            for (int off = 1; off < 32; off <<= 1) {
                int v = __shfl_down_sync(0xFFFFFFFFu, acc, off);
                if (lane + off < 32) acc += v;
            }
            int run = acc - lsum;
#pragma unroll
            for (int j = 7; j >= 0; j--) {
                int above = run;
                if (above < K_rem && above + h[j] >= K_rem) {
                    bin_sh = lane * 8 + j;
                    c_hi_sh = above;
                }
                run += h[j];
            }
        }
        __syncthreads();
        K_rem -= c_hi_sh;
        prefix |= ((uint32_t)bin_sh) << shift;
    }
    __syncthreads();

    const uint32_t u_thr = prefix;
    int myeq = 0;
#pragma unroll
    for (int c = 0; c < NN / 1024; c++) myeq += (su[c * 1024 + tid] == u_thr);
#pragma unroll
    for (int o = 16; o; o >>= 1) myeq += __shfl_xor_sync(0xFFFFFFFFu, myeq, o);
    if (lane == 0 && myeq) atomicAdd(&eq_cnt, myeq);
    __syncthreads();

    if (eq_cnt == K_rem) {
#pragma unroll
        for (int c = 0; c < NN / 1024; c++) {
            const int i = c * 1024 + tid;
            if (su[i] >= u_thr) {
                int slot = atomicAdd(&cnt, 1);
                g_selidx[b * KK + slot] = i;
            }
        }
    } else {
        int running = 0;
#pragma unroll
        for (int c = 0; c < NN / 1024; c++) {
            const int i = c * 1024 + tid;
            const uint32_t u = su[i];
            const bool eq = (u == u_thr);
            if (u > u_thr) {
                int slot = atomicAdd(&cnt, 1);
                g_selidx[b * KK + slot] = i;
            }
            uint32_t bal = __ballot_sync(0xFFFFFFFFu, eq);
            if (lane == 0) wcnt[wid] = __popc(bal);
            __syncthreads();
            if (wid == 0) {
                int v = wcnt[lane], p = v;
#pragma unroll
                for (int off = 1; off < 32; off <<= 1) {
                    int t = __shfl_up_sync(0xFFFFFFFFu, p, off);
                    if (lane >= off) p += t;
                }
                wpre[lane] = p - v;
                if (lane == 31) chunk_tot = p;
            }
            __syncthreads();
            if (eq) {
                int r = running + wpre[wid] + __popc(bal & ((1u << lane) - 1u));
                if (r < K_rem) {
                    int slot = atomicAdd(&cnt, 1);
                    g_selidx[b * KK + slot] = i;
                }
            }
            running += chunk_tot;
            __syncthreads();
        }
    }
}

// ================= fp16 mma GEMM: out[m,n] = X[m,:].W[n,:] + bias[n] =================
#define GA0 0u
#define GA1 2560u
#define GB0 5120u
#define GB1 7680u
#define G_SMEM (10240u * 4u)

__global__ __launch_bounds__(256) void gemm_mma(
    const float* __restrict__ X,
    const float* __restrict__ W0, const float* __restrict__ W1, const float* __restrict__ W2,
    const float* __restrict__ B0, const float* __restrict__ B1, const float* __restrict__ B2,
    float* __restrict__ O0, float* __restrict__ O1, float* __restrict__ O2) {
    extern __shared__ __align__(16) uint32_t sm[];
    const int z = blockIdx.z;
    const float* W = (z == 0) ? W0 : (z == 1) ? W1 : W2;
    const float* bias = (z == 0) ? B0 : (z == 1) ? B1 : B2;
    float* out = (z == 0) ? O0 : (z == 1) ? O1 : O2;

    const int tid = threadIdx.x, lane = tid & 31, wid = tid >> 5;
    const int m0 = blockIdx.x * 128;
    const int n0 = blockIdx.y * 128;
    const int wm = wid & 1, wn = wid >> 1;

    float c[4][4][4];
#pragma unroll
    for (int mf = 0; mf < 4; mf++)
#pragma unroll
        for (int nf = 0; nf < 4; nf++)
#pragma unroll
            for (int j = 0; j < 4; j++) c[mf][nf][j] = 0.f;

    float4 av[4], bv[4];
#pragma unroll
    for (int i = 0; i < 4; i++) {
        int idx = tid + i * 256;
        int r = idx >> 3, c4 = idx & 7;
        av[i] = *(const float4*)(X + (size_t)(m0 + r) * CC + c4 * 4);
        bv[i] = *(const float4*)(W + (size_t)(n0 + r) * CC + c4 * 4);
    }
#pragma unroll
    for (int i = 0; i < 4; i++) {
        int idx = tid + i * 256;
        int r = idx >> 3, c4 = idx & 7;
        uint2 ha = make_uint2(pk2(av[i].x, av[i].y), pk2(av[i].z, av[i].w));
        uint2 hb = make_uint2(pk2(bv[i].x, bv[i].y), pk2(bv[i].z, bv[i].w));
        *(uint2*)&sm[GA0 + r * 20 + c4 * 2] = ha;
        *(uint2*)&sm[GB0 + r * 20 + c4 * 2] = hb;
    }
    __syncthreads();

    for (int ch = 0; ch < 8; ch++) {
        if (ch < 7) {
            int k0 = (ch + 1) * 32;
#pragma unroll
            for (int i = 0; i < 4; i++) {
                int idx = tid + i * 256;
                int r = idx >> 3, c4 = idx & 7;
                av[i] = *(const float4*)(X + (size_t)(m0 + r) * CC + k0 + c4 * 4);
                bv[i] = *(const float4*)(W + (size_t)(n0 + r) * CC + k0 + c4 * 4);
            }
        }
        const uint32_t Ab = (ch & 1) ? GA1 : GA0;
        const uint32_t Bb = (ch & 1) ? GB1 : GB0;
#pragma unroll
        for (int s = 0; s < 2; s++) {
            const uint32_t abase = Ab + (wm * 64 + (lane >> 2)) * 20 + (lane & 3) + s * 8;
            const uint32_t bbase = Bb + (wn * 32 + (lane >> 2)) * 20 + (lane & 3) + s * 8;
            uint32_t a[4][4], b[4][2];
#pragma unroll
            for (int mf = 0; mf < 4; mf++) {
                a[mf][0] = sm[abase + mf * 320];
                a[mf][1] = sm[abase + mf * 320 + 160];
                a[mf][2] = sm[abase + mf * 320 + 4];
                a[mf][3] = sm[abase + mf * 320 + 164];
            }
#pragma unroll
            for (int nf = 0; nf < 4; nf++) {
                b[nf][0] = sm[bbase + nf * 160];
                b[nf][1] = sm[bbase + nf * 160 + 4];
            }
#pragma unroll
            for (int mf = 0; mf < 4; mf++)
#pragma unroll
                for (int nf = 0; nf < 4; nf++) mma16(c[mf][nf], a[mf], b[nf]);
        }
        if (ch < 7) {
            const uint32_t An = (ch & 1) ? GA0 : GA1;
            const uint32_t Bn = (ch & 1) ? GB0 : GB1;
#pragma unroll
            for (int i = 0; i < 4; i++) {
                int idx = tid + i * 256;
                int r = idx >> 3, c4 = idx & 7;
                uint2 ha = make_uint2(pk2(av[i].x, av[i].y), pk2(av[i].z, av[i].w));
                uint2 hb = make_uint2(pk2(bv[i].x, bv[i].y), pk2(bv[i].z, bv[i].w));
                *(uint2*)&sm[An + r * 20 + c4 * 2] = ha;
                *(uint2*)&sm[Bn + r * 20 + c4 * 2] = hb;
            }
            __syncthreads();
        }
    }

#pragma unroll
    for (int nf = 0; nf < 4; nf++) {
        const int col = n0 + wn * 32 + nf * 8 + 2 * (lane & 3);
        const float bi0 = bias[col], bi1 = bias[col + 1];
#pragma unroll
        for (int mf = 0; mf < 4; mf++) {
            const int row = m0 + wm * 64 + mf * 16 + (lane >> 2);
            size_t o0 = (size_t)row * CC + col;
            size_t o1 = (size_t)(row + 8) * CC + col;
            float2 v0, v1;
            v0.x = c[mf][nf][0] + bi0; v0.y = c[mf][nf][1] + bi1;
            v1.x = c[mf][nf][2] + bi0; v1.y = c[mf][nf][3] + bi1;
            *(float2*)(out + o0) = v0;
            *(float2*)(out + o1) = v1;
        }
    }
}

// ================= landmark softmax via fp16 mma (+fused T-accumulate on k side) =================
#define LSEL 0u
#define LA0 5280u
#define LA1 7840u
#define L_SMEM (10400u * 4u)

__global__ __launch_bounds__(256) void lm_mma() {
    extern __shared__ __align__(16) uint32_t sm[];
    const int tid = threadIdx.x, lane = tid & 31, wid = tid >> 5;
    const int m0 = blockIdx.x * 128;
    const int b = m0 >> 13;
    const float* src = blockIdx.y ? g_k : g_q;

#pragma unroll
    for (int i = 0; i < 10; i++) {
        int idx = tid + i * 256;
        int r = idx >> 6, c4 = idx & 63;
        const float* rp = g_k + ((size_t)b * NN + g_selidx[b * KK + r]) * CC;
        float4 v = *(const float4*)(rp + c4 * 4);
        uint2 h = make_uint2(pk2(v.x, v.y), pk2(v.z, v.w));
        *(uint2*)&sm[LSEL + r * 132 + c4 * 2] = h;
    }
    float4 av[4];
#pragma unroll
    for (int i = 0; i < 4; i++) {
        int idx = tid + i * 256;
        int r = idx >> 3, c4 = idx & 7;
        av[i] = *(const float4*)(src + (size_t)(m0 + r) * CC + c4 * 4);
    }
#pragma unroll
    for (int i = 0; i < 4; i++) {
        int idx = tid + i * 256;
        int r = idx >> 3, c4 = idx & 7;
        uint2 ha = make_uint2(pk2(av[i].x, av[i].y), pk2(av[i].z, av[i].w));
        *(uint2*)&sm[LA0 + r * 20 + c4 * 2] = ha;
    }
    __syncthreads();

    float c[5][4];
#pragma unroll
    for (int nf = 0; nf < 5; nf++)
#pragma unroll
        for (int j = 0; j < 4; j++) c[nf][j] = 0.f;

    for (int ch = 0; ch < 8; ch++) {
        if (ch < 7) {
            int k0 = (ch + 1) * 32;
#pragma unroll
            for (int i = 0; i < 4; i++) {
                int idx = tid + i * 256;
                int r = idx >> 3, c4 = idx & 7;
                av[i] = *(const float4*)(src + (size_t)(m0 + r) * CC + k0 + c4 * 4);
            }
        }
        const uint32_t Ab = (ch & 1) ? LA1 : LA0;
#pragma unroll
        for (int s = 0; s < 2; s++) {
            const uint32_t abase = Ab + (wid * 16 + (lane >> 2)) * 20 + (lane & 3) + s * 8;
            const uint32_t sbase = LSEL + (lane >> 2) * 132 + (lane & 3) + ch * 16 + s * 8;
            uint32_t a[4], bfr[5][2];
            a[0] = sm[abase];
            a[1] = sm[abase + 160];
            a[2] = sm[abase + 4];
            a[3] = sm[abase + 164];
#pragma unroll
            for (int nf = 0; nf < 5; nf++) {
                bfr[nf][0] = sm[sbase + nf * 8 * 132];
                bfr[nf][1] = sm[sbase + nf * 8 * 132 + 4];
            }
#pragma unroll
            for (int nf = 0; nf < 5; nf++) mma16(c[nf], a, bfr[nf]);
        }
        if (ch < 7) {
            const uint32_t An = (ch & 1) ? LA0 : LA1;
#pragma unroll
            for (int i = 0; i < 4; i++) {
                int idx = tid + i * 256;
                int r = idx >> 3, c4 = idx & 7;
                uint2 ha = make_uint2(pk2(av[i].x, av[i].y), pk2(av[i].z, av[i].w));
                *(uint2*)&sm[An + r * 20 + c4 * 2] = ha;
            }
            __syncthreads();
        }
    }

    float v0[10], v1[10];
#pragma unroll
    for (int nf = 0; nf < 5; nf++) {
        v0[nf * 2] = c[nf][0]; v0[nf * 2 + 1] = c[nf][1];
        v1[nf * 2] = c[nf][2]; v1[nf * 2 + 1] = c[nf][3];
    }
    float mx0 = v0[0], mx1 = v1[0];
#pragma unroll
    for (int i = 1; i < 10; i++) { mx0 = fmaxf(mx0, v0[i]); mx1 = fmaxf(mx1, v1[i]); }
    mx0 = fmaxf(mx0, __shfl_xor_sync(0xFFFFFFFFu, mx0, 1));
    mx0 = fmaxf(mx0, __shfl_xor_sync(0xFFFFFFFFu, mx0, 2));
    mx1 = fmaxf(mx1, __shfl_xor_sync(0xFFFFFFFFu, mx1, 1));
    mx1 = fmaxf(mx1, __shfl_xor_sync(0xFFFFFFFFu, mx1, 2));
    float s0 = 0.f, s1 = 0.f;
#pragma unroll
    for (int i = 0; i < 10; i++) {
        v0[i] = __expf((v0[i] - mx0) * 0.0625f); s0 += v0[i];
        v1[i] = __expf((v1[i] - mx1) * 0.0625f); s1 += v1[i];
    }
    s0 += __shfl_xor_sync(0xFFFFFFFFu, s0, 1);
    s0 += __shfl_xor_sync(0xFFFFFFFFu, s0, 2);
    s1 += __shfl_xor_sync(0xFFFFFFFFu, s1, 1);
    s1 += __shfl_xor_sync(0xFFFFFFFFu, s1, 2);
    const float i0 = 1.f / s0, i1 = 1.f / s1;
    const int lr0 = wid * 16 + (lane >> 2);

    if (blockIdx.y == 0) {
#pragma unroll
        for (int nf = 0; nf < 5; nf++) {
            int col = nf * 8 + 2 * (lane & 3);
            float2 w0, w1;
            w0.x = v0[nf * 2] * i0; w0.y = v0[nf * 2 + 1] * i0;
            w1.x = v1[nf * 2] * i1; w1.y = v1[nf * 2 + 1] * i1;
            *(float2*)&g_Pq[(size_t)(m0 + lr0) * KK + col] = w0;
            *(float2*)&g_Pq[(size_t)(m0 + lr0 + 8) * KK + col] = w1;
        }
    } else {
        __syncthreads();
        float* Psh = (float*)&sm[LA0];
#pragma unroll
        for (int nf = 0; nf < 5; nf++) {
            int col = nf * 8 + 2 * (lane & 3);
            Psh[lr0 * KK + col] = v0[nf * 2] * i0;
            Psh[lr0 * KK + col + 1] = v0[nf * 2 + 1] * i0;
            Psh[(lr0 + 8) * KK + col] = v1[nf * 2] * i1;
            Psh[(lr0 + 8) * KK + col + 1] = v1[nf * 2 + 1] * i1;
        }
        __syncthreads();
        const int cc = tid;
        float acc[KK];
#pragma unroll
        for (int j = 0; j < KK; j++) acc[j] = 0.f;
        const float* v = &g_v[(size_t)m0 * CC + cc];
        for (int n = 0; n < 128; n++) {
            float val = v[(size_t)n * CC];
            const float* pr = &Psh[n * KK];
#pragma unroll
            for (int j = 0; j < KK; j += 4) {
                float4 p = *(const float4*)&pr[j];
                acc[j + 0] += p.x * val; acc[j + 1] += p.y * val;
                acc[j + 2] += p.z * val; acc[j + 3] += p.w * val;
            }
        }
        float* T = &g_T[(size_t)b * KK * CC + cc];
#pragma unroll
        for (int j = 0; j < KK; j++) atomicAdd(&T[j * CC], acc[j]);
    }
}

// ================= T2 = T @ Wo^T  (tiny: B x 40 x 256, fp32 exact) =================
__global__ __launch_bounds__(256) void t2_kernel(const float* __restrict__ Wo) {
    __shared__ float t[CC];
    const int b = blockIdx.x, j = blockIdx.y, c = threadIdx.x;
    t[c] = g_T[((size_t)b * KK + j) * CC + c];
    __syncthreads();
    const float4* w = (const float4*)(Wo + (size_t)c * CC);
    const float4* ts = (const float4*)t;
    float s = 0.f;
#pragma unroll 8
    for (int d = 0; d < CC / 4; d++) {
        float4 wv = w[d], tv = ts[d];
        s += wv.x * tv.x + wv.y * tv.y + wv.z * tv.z + wv.w * tv.w;
    }
    g_T2[((size_t)b * KK + j) * CC + c] = s;
}

// ================= final output: out = Pq @ T2 + bo + query =================
__global__ __launch_bounds__(256) void out_kernel(const float* __restrict__ query,
                                                  const float* __restrict__ bo,
                                                  float* __restrict__ out) {
    __shared__ float P_sh[128 * KK];
    int b = blockIdx.y;
    int n0 = blockIdx.x * 128;
    int c = threadIdx.x;
    const float* Pg = &g_Pq[((size_t)b * NN + n0) * KK];
    for (int i = c * 4; i < 128 * KK; i += 1024)
        *(float4*)&P_sh[i] = *(const float4*)&Pg[i];
    float t[KK];
    const float* T2 = &g_T2[(size_t)b * KK * CC + c];
#pragma unroll
    for (int j = 0; j < KK; j++) t[j] = T2[j * CC];
    const float bias = bo[c];
    __syncthreads();
    const float* q = query + ((size_t)b * NN + n0) * CC + c;
    float* o = out + ((size_t)b * NN + n0) * CC + c;
    for (int n = 0; n < 128; n++) {
        const float* pr = &P_sh[n * KK];
        float s = 0.f;
#pragma unroll
        for (int j = 0; j < KK; j += 4) {
            float4 p = *(const float4*)&pr[j];
            s += p.x * t[j + 0] + p.y * t[j + 1] + p.z * t[j + 2] + p.w * t[j + 3];
        }
        o[(size_t)n * CC] = s + bias + q[(size_t)n * CC];
    }
}

// ================= launch =================
extern "C" void kernel_launch(void* const* d_in, const int* in_sizes, int n_in,
                              void* d_out, int out_size) {
    (void)in_sizes; (void)n_in; (void)out_size;
    const float* query = (const float*)d_in[0];
    const float* Wq = (const float*)d_in[1];
    const float* bq = (const float*)d_in[2];
    const float* Wk = (const float*)d_in[3];
    const float* bk = (const float*)d_in[4];
    const float* Wv = (const float*)d_in[5];
    const float* bv = (const float*)d_in[6];
    const float* Wo = (const float*)d_in[7];
    const float* bo = (const float*)d_in[8];
    float* out = (float*)d_out;

    cudaFuncSetAttribute(gemm_mma, cudaFuncAttributeMaxDynamicSharedMemorySize, G_SMEM);
    cudaFuncSetAttribute(lm_mma, cudaFuncAttributeMaxDynamicSharedMemorySize, L_SMEM);

    float *p_q, *p_k, *p_v;
    cudaGetSymbolAddress((void**)&p_q, g_q);
    cudaGetSymbolAddress((void**)&p_k, g_k);
    cudaGetSymbolAddress((void**)&p_v, g_v);

    // Fork: small latency-bound selection chain overlaps the QKV GEMM.
    cudaStream_t s2;
    cudaEvent_t e1, e2;
    cudaStreamCreateWithFlags(&s2, cudaStreamNonBlocking);
    cudaEventCreateWithFlags(&e1, cudaEventDisableTiming);
    cudaEventCreateWithFlags(&e2, cudaEventDisableTiming);

    cudaEventRecord(e1, 0);
    cudaStreamWaitEvent(s2, e1, 0);

    xsum_kernel<<<64, 256, 0, s2>>>(query);
    prep_kernel<<<BB, 256, 0, s2>>>(Wq, bq, Wk);
    score_kernel<<<MM / 8, 256, 0, s2>>>(query);
    topk_kernel<<<BB, 1024, 0, s2>>>();
    cudaEventRecord(e2, s2);

    dim3 gqkv(MM / 128, CC / 128, 3);
    gemm_mma<<<gqkv, 256, G_SMEM>>>(query, Wq, Wk, Wv, bq, bk, bv, p_q, p_k, p_v);

    cudaStreamWaitEvent(0, e2, 0);

    lm_mma<<<dim3(MM / 128, 2), 256, L_SMEM>>>();

    t2_kernel<<<dim3(BB, KK), 256>>>(Wo);

    dim3 gt(NN / 128, BB);
    out_kernel<<<gt, 256>>>(query, bo, out);

    cudaStreamDestroy(s2);
    cudaEventDestroy(e1);
    cudaEventDestroy(e2);
}

// round 11
// speedup vs baseline: 1.0615x; 1.0615x over previous
#include <cuda_runtime.h>
#include <cuda_fp16.h>
#include <cstdint>

#define BB 2
#define NN 8192
#define CC 256
#define KK 40
#define MM (BB * NN)

// ================= scratch =================
__device__ float g_q[MM * CC];
__device__ float g_k[MM * CC];
__device__ float g_v[MM * CC];
__device__ float g_part[BB * 32 * CC];
__device__ float g_u[BB * CC];
__device__ float g_score[BB * NN];
__device__ int   g_selidx[BB * KK];
__device__ float g_T[BB * KK * CC];
__device__ float g_T2[BB * KK * CC];
__device__ float g_Pq[MM * KK];

// ================= helpers (family-portable PTX only) =================
__device__ __forceinline__ uint32_t pk2(float lo, float hi) {
    __half2 h = __floats2half2_rn(lo, hi);
    return *reinterpret_cast<uint32_t*>(&h);
}
__device__ __forceinline__ void mma16(float* c, const uint32_t* a, const uint32_t* b) {
    asm volatile(
        "mma.sync.aligned.m16n8k16.row.col.f32.f16.f16.f32 "
        "{%0,%1,%2,%3}, {%4,%5,%6,%7}, {%8,%9}, {%0,%1,%2,%3};"
        : "+f"(c[0]), "+f"(c[1]), "+f"(c[2]), "+f"(c[3])
        : "r"(a[0]), "r"(a[1]), "r"(a[2]), "r"(a[3]), "r"(b[0]), "r"(b[1]));
}

// ================= xsum: per-chunk partial column sums + zero g_T =================
__global__ __launch_bounds__(256) void xsum_kernel(const float* __restrict__ x) {
    __shared__ float4 red[4][64];
    int b = blockIdx.x >> 5, chunk = blockIdx.x & 31;
    int c4 = threadIdx.x & 63, rl = threadIdx.x >> 6;
    const float* base = x + ((size_t)b * NN + chunk * 256 + rl) * CC + c4 * 4;
    float4 s = make_float4(0.f, 0.f, 0.f, 0.f);
#pragma unroll 8
    for (int n = 0; n < 64; n++) {
        float4 v = *(const float4*)(base + (size_t)n * 4 * CC);
        s.x += v.x; s.y += v.y; s.z += v.z; s.w += v.w;
    }
    red[rl][c4] = s;
    for (int i = blockIdx.x * 256 + threadIdx.x; i < BB * KK * CC; i += 64 * 256)
        g_T[i] = 0.f;
    __syncthreads();
    if (rl == 0) {
        float4 a = red[0][c4], b2 = red[1][c4], c2 = red[2][c4], d = red[3][c4];
        float4 o;
        o.x = a.x + b2.x + c2.x + d.x; o.y = a.y + b2.y + c2.y + d.y;
        o.z = a.z + b2.z + c2.z + d.z; o.w = a.w + b2.w + c2.w + d.w;
        *(float4*)&g_part[(size_t)(b * 32 + chunk) * CC + c4 * 4] = o;
    }
}

// qsum = Wq*xsum + N*bq (fp32 exact), then u = Wk^T * qsum
__global__ void prep_kernel(const float* __restrict__ Wq, const float* __restrict__ bq,
                            const float* __restrict__ Wk) {
    __shared__ float xs[CC], qs[CC];
    int b = blockIdx.x, tid = threadIdx.x, w = tid >> 5, lane = tid & 31;
    float sx = 0.f;
#pragma unroll 8
    for (int ch = 0; ch < 32; ch++) sx += g_part[(size_t)(b * 32 + ch) * CC + tid];
    xs[tid] = sx;
    __syncthreads();
    for (int c = w * 32; c < w * 32 + 32; c++) {
        const float* wr = Wq + (size_t)c * CC;
        float s = 0.f;
#pragma unroll
        for (int i = 0; i < 8; i++) s += xs[lane + 32 * i] * wr[lane + 32 * i];
#pragma unroll
        for (int o = 16; o; o >>= 1) s += __shfl_xor_sync(0xFFFFFFFFu, s, o);
        if (lane == 0) qs[c] = s + (float)NN * bq[c];
    }
    __syncthreads();
    int c = tid;
    float u = 0.f;
#pragma unroll 8
    for (int d = 0; d < CC; d++) u += qs[d] * Wk[(size_t)d * CC + c];
    g_u[b * CC + c] = u;
}

// score_m = u_b . x_m  (order-identical to qsum.k_m/16 up to constant; exact fp32)
__global__ void score_kernel(const float* __restrict__ x) {
    int warp = threadIdx.x >> 5, lane = threadIdx.x & 31;
    int row = blockIdx.x * 8 + warp;
    int b = row >> 13;
    const float4* xr = (const float4*)(x + (size_t)row * CC);
    const float4* u = (const float4*)(&g_u[b * CC]);
    float4 v0 = xr[lane], v1 = xr[lane + 32];
    float4 u0 = u[lane], u1 = u[lane + 32];
    float s = v0.x * u0.x + v0.y * u0.y + v0.z * u0.z + v0.w * u0.w
            + v1.x * u1.x + v1.y * u1.y + v1.z * u1.z + v1.w * u1.w;
#pragma unroll
    for (int o = 16; o; o >>= 1) s += __shfl_xor_sync(0xFFFFFFFFu, s, o);
    if (lane == 0) g_score[row] = s;
}

// ================= exact top-40 via radix-256 select (one CTA per batch) =================
__global__ __launch_bounds__(1024) void topk_kernel() {
    __shared__ uint32_t su[NN];
    __shared__ int hist[256];
    __shared__ int c_hi_sh, bin_sh, cnt, chunk_tot, eq_cnt;
    __shared__ int wcnt[32], wpre[32];
    const int b = blockIdx.x, tid = threadIdx.x, lane = tid & 31, wid = tid >> 5;

    for (int i = tid; i < NN; i += 1024) {
        uint32_t u = __float_as_uint(g_score[b * NN + i]);
        su[i] = (u & 0x80000000u) ? ~u : (u | 0x80000000u);
    }
    if (tid == 0) { cnt = 0; eq_cnt = 0; }

    uint32_t prefix = 0;
    int K_rem = KK;
#pragma unroll
    for (int shift = 24; shift >= 0; shift -= 8) {
        __syncthreads();
        if (tid < 256) hist[tid] = 0;
        __syncthreads();
        const uint32_t mask_hi = (shift == 24) ? 0u : (0xFFFFFFFFu << (shift + 8));
#pragma unroll
        for (int c = 0; c < NN / 1024; c++) {
            uint32_t u = su[c * 1024 + tid];
            int bin = ((u & mask_hi) == prefix) ? (int)((u >> shift) & 0xFF) : 256;
            uint32_t grp = __match_any_sync(0xFFFFFFFFu, bin);
            if (bin < 256 && (__ffs(grp) - 1) == lane) atomicAdd(&hist[bin], __popc(grp));
        }
        __syncthreads();
        if (wid == 0) {
            int h[8], lsum = 0;
#pragma unroll
            for (int j = 0; j < 8; j++) { h[j] = hist[lane * 8 + j]; lsum += h[j]; }
            int acc = lsum;
#pragma unroll
            for (int off = 1; off < 32; off <<= 1) {
                int v = __shfl_down_sync(0xFFFFFFFFu, acc, off);
                if (lane + off < 32) acc += v;
            }
            int run = acc - lsum;
#pragma unroll
            for (int j = 7; j >= 0; j--) {
                int above = run;
                if (above < K_rem && above + h[j] >= K_rem) {
                    bin_sh = lane * 8 + j;
                    c_hi_sh = above;
                }
                run += h[j];
            }
        }
        __syncthreads();
        K_rem -= c_hi_sh;
        prefix |= ((uint32_t)bin_sh) << shift;
    }
    __syncthreads();

    const uint32_t u_thr = prefix;
    int myeq = 0;
#pragma unroll
    for (int c = 0; c < NN / 1024; c++) myeq += (su[c * 1024 + tid] == u_thr);
#pragma unroll
    for (int o = 16; o; o >>= 1) myeq += __shfl_xor_sync(0xFFFFFFFFu, myeq, o);
    if (lane == 0 && myeq) atomicAdd(&eq_cnt, myeq);
    __syncthreads();

    if (eq_cnt == K_rem) {
#pragma unroll
        for (int c = 0; c < NN / 1024; c++) {
            const int i = c * 1024 + tid;
            if (su[i] >= u_thr) {
                int slot = atomicAdd(&cnt, 1);
                g_selidx[b * KK + slot] = i;
            }
        }
    } else {
        int running = 0;
#pragma unroll
        for (int c = 0; c < NN / 1024; c++) {
            const int i = c * 1024 + tid;
            const uint32_t u = su[i];
            const bool eq = (u == u_thr);
            if (u > u_thr) {
                int slot = atomicAdd(&cnt, 1);
                g_selidx[b * KK + slot] = i;
            }
            uint32_t bal = __ballot_sync(0xFFFFFFFFu, eq);
            if (lane == 0) wcnt[wid] = __popc(bal);
            __syncthreads();
            if (wid == 0) {
                int v = wcnt[lane], p = v;
#pragma unroll
                for (int off = 1; off < 32; off <<= 1) {
                    int t = __shfl_up_sync(0xFFFFFFFFu, p, off);
                    if (lane >= off) p += t;
                }
                wpre[lane] = p - v;
                if (lane == 31) chunk_tot = p;
            }
            __syncthreads();
            if (eq) {
                int r = running + wpre[wid] + __popc(bal & ((1u << lane) - 1u));
                if (r < K_rem) {
                    int slot = atomicAdd(&cnt, 1);
                    g_selidx[b * KK + slot] = i;
                }
            }
            running += chunk_tot;
            __syncthreads();
        }
    }
}

// ================= fp16 mma GEMM: out[m,n] = X[m,:].W[n,:] + bias[n] =================
#define GA0 0u
#define GA1 2560u
#define GB0 5120u
#define GB1 7680u
#define G_SMEM (10240u * 4u)

__global__ __launch_bounds__(256) void gemm_mma(
    const float* __restrict__ X,
    const float* __restrict__ W0, const float* __restrict__ W1, const float* __restrict__ W2,
    const float* __restrict__ B0, const float* __restrict__ B1, const float* __restrict__ B2,
    float* __restrict__ O0, float* __restrict__ O1, float* __restrict__ O2) {
    extern __shared__ __align__(16) uint32_t sm[];
    const int z = blockIdx.z;
    const float* W = (z == 0) ? W0 : (z == 1) ? W1 : W2;
    const float* bias = (z == 0) ? B0 : (z == 1) ? B1 : B2;
    float* out = (z == 0) ? O0 : (z == 1) ? O1 : O2;

    const int tid = threadIdx.x, lane = tid & 31, wid = tid >> 5;
    const int m0 = blockIdx.x * 128;
    const int n0 = blockIdx.y * 128;
    const int wm = wid & 1, wn = wid >> 1;

    float c[4][4][4];
#pragma unroll
    for (int mf = 0; mf < 4; mf++)
#pragma unroll
        for (int nf = 0; nf < 4; nf++)
#pragma unroll
            for (int j = 0; j < 4; j++) c[mf][nf][j] = 0.f;

    float4 av[4], bv[4];
#pragma unroll
    for (int i = 0; i < 4; i++) {
        int idx = tid + i * 256;
        int r = idx >> 3, c4 = idx & 7;
        av[i] = *(const float4*)(X + (size_t)(m0 + r) * CC + c4 * 4);
        bv[i] = *(const float4*)(W + (size_t)(n0 + r) * CC + c4 * 4);
    }
#pragma unroll
    for (int i = 0; i < 4; i++) {
        int idx = tid + i * 256;
        int r = idx >> 3, c4 = idx & 7;
        uint2 ha = make_uint2(pk2(av[i].x, av[i].y), pk2(av[i].z, av[i].w));
        uint2 hb = make_uint2(pk2(bv[i].x, bv[i].y), pk2(bv[i].z, bv[i].w));
        *(uint2*)&sm[GA0 + r * 20 + c4 * 2] = ha;
        *(uint2*)&sm[GB0 + r * 20 + c4 * 2] = hb;
    }
    __syncthreads();

    for (int ch = 0; ch < 8; ch++) {
        if (ch < 7) {
            int k0 = (ch + 1) * 32;
#pragma unroll
            for (int i = 0; i < 4; i++) {
                int idx = tid + i * 256;
                int r = idx >> 3, c4 = idx & 7;
                av[i] = *(const float4*)(X + (size_t)(m0 + r) * CC + k0 + c4 * 4);
                bv[i] = *(const float4*)(W + (size_t)(n0 + r) * CC + k0 + c4 * 4);
            }
        }
        const uint32_t Ab = (ch & 1) ? GA1 : GA0;
        const uint32_t Bb = (ch & 1) ? GB1 : GB0;
#pragma unroll
        for (int s = 0; s < 2; s++) {
            const uint32_t abase = Ab + (wm * 64 + (lane >> 2)) * 20 + (lane & 3) + s * 8;
            const uint32_t bbase = Bb + (wn * 32 + (lane >> 2)) * 20 + (lane & 3) + s * 8;
            uint32_t a[4][4], b[4][2];
#pragma unroll
            for (int mf = 0; mf < 4; mf++) {
                a[mf][0] = sm[abase + mf * 320];
                a[mf][1] = sm[abase + mf * 320 + 160];
                a[mf][2] = sm[abase + mf * 320 + 4];
                a[mf][3] = sm[abase + mf * 320 + 164];
            }
#pragma unroll
            for (int nf = 0; nf < 4; nf++) {
                b[nf][0] = sm[bbase + nf * 160];
                b[nf][1] = sm[bbase + nf * 160 + 4];
            }
#pragma unroll
            for (int mf = 0; mf < 4; mf++)
#pragma unroll
                for (int nf = 0; nf < 4; nf++) mma16(c[mf][nf], a[mf], b[nf]);
        }
        if (ch < 7) {
            const uint32_t An = (ch & 1) ? GA0 : GA1;
            const uint32_t Bn = (ch & 1) ? GB0 : GB1;
#pragma unroll
            for (int i = 0; i < 4; i++) {
                int idx = tid + i * 256;
                int r = idx >> 3, c4 = idx & 7;
                uint2 ha = make_uint2(pk2(av[i].x, av[i].y), pk2(av[i].z, av[i].w));
                uint2 hb = make_uint2(pk2(bv[i].x, bv[i].y), pk2(bv[i].z, bv[i].w));
                *(uint2*)&sm[An + r * 20 + c4 * 2] = ha;
                *(uint2*)&sm[Bn + r * 20 + c4 * 2] = hb;
            }
            __syncthreads();
        }
    }

#pragma unroll
    for (int nf = 0; nf < 4; nf++) {
        const int col = n0 + wn * 32 + nf * 8 + 2 * (lane & 3);
        const float bi0 = bias[col], bi1 = bias[col + 1];
#pragma unroll
        for (int mf = 0; mf < 4; mf++) {
            const int row = m0 + wm * 64 + mf * 16 + (lane >> 2);
            size_t o0 = (size_t)row * CC + col;
            size_t o1 = (size_t)(row + 8) * CC + col;
            float2 v0, v1;
            v0.x = c[mf][nf][0] + bi0; v0.y = c[mf][nf][1] + bi1;
            v1.x = c[mf][nf][2] + bi0; v1.y = c[mf][nf][3] + bi1;
            *(float2*)(out + o0) = v0;
            *(float2*)(out + o1) = v1;
        }
    }
}

// ================= landmark softmax via fp16 mma (+fused T-accumulate on k side) =================
#define LSEL 0u
#define LA0 5280u
#define LA1 7840u
#define L_SMEM (10400u * 4u)

__global__ __launch_bounds__(256) void lm_mma() {
    extern __shared__ __align__(16) uint32_t sm[];
    const int tid = threadIdx.x, lane = tid & 31, wid = tid >> 5;
    const int m0 = blockIdx.x * 128;
    const int b = m0 >> 13;
    const float* src = blockIdx.y ? g_k : g_q;

#pragma unroll
    for (int i = 0; i < 10; i++) {
        int idx = tid + i * 256;
        int r = idx >> 6, c4 = idx & 63;
        const float* rp = g_k + ((size_t)b * NN + g_selidx[b * KK + r]) * CC;
        float4 v = *(const float4*)(rp + c4 * 4);
        uint2 h = make_uint2(pk2(v.x, v.y), pk2(v.z, v.w));
        *(uint2*)&sm[LSEL + r * 132 + c4 * 2] = h;
    }
    float4 av[4];
#pragma unroll
    for (int i = 0; i < 4; i++) {
        int idx = tid + i * 256;
        int r = idx >> 3, c4 = idx & 7;
        av[i] = *(const float4*)(src + (size_t)(m0 + r) * CC + c4 * 4);
    }
#pragma unroll
    for (int i = 0; i < 4; i++) {
        int idx = tid + i * 256;
        int r = idx >> 3, c4 = idx & 7;
        uint2 ha = make_uint2(pk2(av[i].x, av[i].y), pk2(av[i].z, av[i].w));
        *(uint2*)&sm[LA0 + r * 20 + c4 * 2] = ha;
    }
    __syncthreads();

    float c[5][4];
#pragma unroll
    for (int nf = 0; nf < 5; nf++)
#pragma unroll
        for (int j = 0; j < 4; j++) c[nf][j] = 0.f;

    for (int ch = 0; ch < 8; ch++) {
        if (ch < 7) {
            int k0 = (ch + 1) * 32;
#pragma unroll
            for (int i = 0; i < 4; i++) {
                int idx = tid + i * 256;
                int r = idx >> 3, c4 = idx & 7;
                av[i] = *(const float4*)(src + (size_t)(m0 + r) * CC + k0 + c4 * 4);
            }
        }
        const uint32_t Ab = (ch & 1) ? LA1 : LA0;
#pragma unroll
        for (int s = 0; s < 2; s++) {
            const uint32_t abase = Ab + (wid * 16 + (lane >> 2)) * 20 + (lane & 3) + s * 8;
            const uint32_t sbase = LSEL + (lane >> 2) * 132 + (lane & 3) + ch * 16 + s * 8;
            uint32_t a[4], bfr[5][2];
            a[0] = sm[abase];
            a[1] = sm[abase + 160];
            a[2] = sm[abase + 4];
            a[3] = sm[abase + 164];
#pragma unroll
            for (int nf = 0; nf < 5; nf++) {
                bfr[nf][0] = sm[sbase + nf * 8 * 132];
                bfr[nf][1] = sm[sbase + nf * 8 * 132 + 4];
            }
#pragma unroll
            for (int nf = 0; nf < 5; nf++) mma16(c[nf], a, bfr[nf]);
        }
        if (ch < 7) {
            const uint32_t An = (ch & 1) ? LA0 : LA1;
#pragma unroll
            for (int i = 0; i < 4; i++) {
                int idx = tid + i * 256;
                int r = idx >> 3, c4 = idx & 7;
                uint2 ha = make_uint2(pk2(av[i].x, av[i].y), pk2(av[i].z, av[i].w));
                *(uint2*)&sm[An + r * 20 + c4 * 2] = ha;
            }
            __syncthreads();
        }
    }

    float v0[10], v1[10];
#pragma unroll
    for (int nf = 0; nf < 5; nf++) {
        v0[nf * 2] = c[nf][0]; v0[nf * 2 + 1] = c[nf][1];
        v1[nf * 2] = c[nf][2]; v1[nf * 2 + 1] = c[nf][3];
    }
    float mx0 = v0[0], mx1 = v1[0];
#pragma unroll
    for (int i = 1; i < 10; i++) { mx0 = fmaxf(mx0, v0[i]); mx1 = fmaxf(mx1, v1[i]); }
    mx0 = fmaxf(mx0, __shfl_xor_sync(0xFFFFFFFFu, mx0, 1));
    mx0 = fmaxf(mx0, __shfl_xor_sync(0xFFFFFFFFu, mx0, 2));
    mx1 = fmaxf(mx1, __shfl_xor_sync(0xFFFFFFFFu, mx1, 1));
    mx1 = fmaxf(mx1, __shfl_xor_sync(0xFFFFFFFFu, mx1, 2));
    float s0 = 0.f, s1 = 0.f;
#pragma unroll
    for (int i = 0; i < 10; i++) {
        v0[i] = __expf((v0[i] - mx0) * 0.0625f); s0 += v0[i];
        v1[i] = __expf((v1[i] - mx1) * 0.0625f); s1 += v1[i];
    }
    s0 += __shfl_xor_sync(0xFFFFFFFFu, s0, 1);
    s0 += __shfl_xor_sync(0xFFFFFFFFu, s0, 2);
    s1 += __shfl_xor_sync(0xFFFFFFFFu, s1, 1);
    s1 += __shfl_xor_sync(0xFFFFFFFFu, s1, 2);
    const float i0 = 1.f / s0, i1 = 1.f / s1;
    const int lr0 = wid * 16 + (lane >> 2);

    if (blockIdx.y == 0) {
#pragma unroll
        for (int nf = 0; nf < 5; nf++) {
            int col = nf * 8 + 2 * (lane & 3);
            float2 w0, w1;
            w0.x = v0[nf * 2] * i0; w0.y = v0[nf * 2 + 1] * i0;
            w1.x = v1[nf * 2] * i1; w1.y = v1[nf * 2 + 1] * i1;
            *(float2*)&g_Pq[(size_t)(m0 + lr0) * KK + col] = w0;
            *(float2*)&g_Pq[(size_t)(m0 + lr0 + 8) * KK + col] = w1;
        }
    } else {
        __syncthreads();
        float* Psh = (float*)&sm[LA0];
#pragma unroll
        for (int nf = 0; nf < 5; nf++) {
            int col = nf * 8 + 2 * (lane & 3);
            Psh[lr0 * KK + col] = v0[nf * 2] * i0;
            Psh[lr0 * KK + col + 1] = v0[nf * 2 + 1] * i0;
            Psh[(lr0 + 8) * KK + col] = v1[nf * 2] * i1;
            Psh[(lr0 + 8) * KK + col + 1] = v1[nf * 2 + 1] * i1;
        }
        __syncthreads();
        const int cc = tid;
        float acc[KK];
#pragma unroll
        for (int j = 0; j < KK; j++) acc[j] = 0.f;
        const float* v = &g_v[(size_t)m0 * CC + cc];
        for (int n = 0; n < 128; n++) {
            float val = v[(size_t)n * CC];
            const float* pr = &Psh[n * KK];
#pragma unroll
            for (int j = 0; j < KK; j += 4) {
                float4 p = *(const float4*)&pr[j];
                acc[j + 0] += p.x * val; acc[j + 1] += p.y * val;
                acc[j + 2] += p.z * val; acc[j + 3] += p.w * val;
            }
        }
        float* T = &g_T[(size_t)b * KK * CC + cc];
#pragma unroll
        for (int j = 0; j < KK; j++) atomicAdd(&T[j * CC], acc[j]);
    }
}

// ================= T2 = T @ Wo^T  (warp-per-column, coalesced Wo loads) =================
__global__ __launch_bounds__(256) void t2_kernel(const float* __restrict__ Wo) {
    __shared__ float t[CC];
    const int b = blockIdx.x / KK, j = blockIdx.x % KK;
    const int tid = threadIdx.x, lane = tid & 31, wid = tid >> 5;
    t[tid] = g_T[((size_t)b * KK + j) * CC + tid];
    __syncthreads();
    const float4* ts = (const float4*)t;
    for (int c = wid; c < CC; c += 8) {
        const float4* w4 = (const float4*)(Wo + (size_t)c * CC);
        float4 wa = w4[lane], wb = w4[lane + 32];
        float4 ta = ts[lane], tb = ts[lane + 32];
        float s = wa.x * ta.x + wa.y * ta.y + wa.z * ta.z + wa.w * ta.w
                + wb.x * tb.x + wb.y * tb.y + wb.z * tb.z + wb.w * tb.w;
#pragma unroll
        for (int o = 16; o; o >>= 1) s += __shfl_xor_sync(0xFFFFFFFFu, s, o);
        if (lane == 0) g_T2[((size_t)b * KK + j) * CC + c] = s;
    }
}

// ================= final output: out = Pq @ T2 + bo + query (MLP-8 residual loads) =================
__global__ __launch_bounds__(256) void out_kernel(const float* __restrict__ query,
                                                  const float* __restrict__ bo,
                                                  float* __restrict__ out) {
    __shared__ float P_sh[128 * KK];
    int b = blockIdx.y;
    int n0 = blockIdx.x * 128;
    int c = threadIdx.x;
    const float* Pg = &g_Pq[((size_t)b * NN + n0) * KK];
    for (int i = c * 4; i < 128 * KK; i += 1024)
        *(float4*)&P_sh[i] = *(const float4*)&Pg[i];
    float t[KK];
    const float* T2 = &g_T2[(size_t)b * KK * CC + c];
#pragma unroll
    for (int j = 0; j < KK; j++) t[j] = T2[j * CC];
    const float bias = bo[c];
    __syncthreads();
    const float* q = query + ((size_t)b * NN + n0) * CC + c;
    float* o = out + ((size_t)b * NN + n0) * CC + c;
    for (int nb = 0; nb < 128; nb += 8) {
        float qv[8];
#pragma unroll
        for (int m = 0; m < 8; m++) qv[m] = q[(size_t)(nb + m) * CC];   // 8 outstanding loads
#pragma unroll
        for (int m = 0; m < 8; m++) {
            const float* pr = &P_sh[(nb + m) * KK];
            float s = 0.f;
#pragma unroll
            for (int j = 0; j < KK; j += 4) {
                float4 p = *(const float4*)&pr[j];
                s += p.x * t[j + 0] + p.y * t[j + 1] + p.z * t[j + 2] + p.w * t[j + 3];
            }
            o[(size_t)(nb + m) * CC] = s + bias + qv[m];
        }
    }
}

// ================= launch =================
extern "C" void kernel_launch(void* const* d_in, const int* in_sizes, int n_in,
                              void* d_out, int out_size) {
    (void)in_sizes; (void)n_in; (void)out_size;
    const float* query = (const float*)d_in[0];
    const float* Wq = (const float*)d_in[1];
    const float* bq = (const float*)d_in[2];
    const float* Wk = (const float*)d_in[3];
    const float* bk = (const float*)d_in[4];
    const float* Wv = (const float*)d_in[5];
    const float* bv = (const float*)d_in[6];
    const float* Wo = (const float*)d_in[7];
    const float* bo = (const float*)d_in[8];
    float* out = (float*)d_out;

    cudaFuncSetAttribute(gemm_mma, cudaFuncAttributeMaxDynamicSharedMemorySize, G_SMEM);
    cudaFuncSetAttribute(lm_mma, cudaFuncAttributeMaxDynamicSharedMemorySize, L_SMEM);

    float *p_q, *p_k, *p_v;
    cudaGetSymbolAddress((void**)&p_q, g_q);
    cudaGetSymbolAddress((void**)&p_k, g_k);
    cudaGetSymbolAddress((void**)&p_v, g_v);

    // Fork: small latency-bound selection chain overlaps the QKV GEMM.
    cudaStream_t s2;
    cudaEvent_t e1, e2;
    cudaStreamCreateWithFlags(&s2, cudaStreamNonBlocking);
    cudaEventCreateWithFlags(&e1, cudaEventDisableTiming);
    cudaEventCreateWithFlags(&e2, cudaEventDisableTiming);

    cudaEventRecord(e1, 0);
    cudaStreamWaitEvent(s2, e1, 0);

    xsum_kernel<<<64, 256, 0, s2>>>(query);
    prep_kernel<<<BB, 256, 0, s2>>>(Wq, bq, Wk);
    score_kernel<<<MM / 8, 256, 0, s2>>>(query);
    topk_kernel<<<BB, 1024, 0, s2>>>();
    cudaEventRecord(e2, s2);

    dim3 gqkv(MM / 128, CC / 128, 3);
    gemm_mma<<<gqkv, 256, G_SMEM>>>(query, Wq, Wk, Wv, bq, bk, bv, p_q, p_k, p_v);

    cudaStreamWaitEvent(0, e2, 0);

    lm_mma<<<dim3(MM / 128, 2), 256, L_SMEM>>>();

    t2_kernel<<<BB * KK, 256>>>(Wo);

    dim3 gt(NN / 128, BB);
    out_kernel<<<gt, 256>>>(query, bo, out);

    cudaStreamDestroy(s2);
    cudaEventDestroy(e1);
    cudaEventDestroy(e2);
}

// round 12
// speedup vs baseline: 1.1735x; 1.1056x over previous
#include <cuda_runtime.h>
#include <cuda_fp16.h>
#include <cstdint>

#define BB 2
#define NN 8192
#define CC 256
#define KK 40
#define MM (BB * NN)

// ================= scratch =================
__device__ float g_q[MM * CC];
__device__ float g_k[MM * CC];
__device__ float g_v[MM * CC];
__device__ float g_part[BB * 32 * CC];
__device__ float g_u[BB * CC];
__device__ float g_score[BB * NN];
__device__ int   g_selidx[BB * KK];
__device__ float g_T[BB * KK * CC];
__device__ float g_T2[BB * KK * CC];
__device__ float g_Pq[MM * KK];

// ================= helpers (family-portable PTX only) =================
__device__ __forceinline__ uint32_t pk2(float lo, float hi) {
    __half2 h = __floats2half2_rn(lo, hi);
    return *reinterpret_cast<uint32_t*>(&h);
}
__device__ __forceinline__ void mma16(float* c, const uint32_t* a, const uint32_t* b) {
    asm volatile(
        "mma.sync.aligned.m16n8k16.row.col.f32.f16.f16.f32 "
        "{%0,%1,%2,%3}, {%4,%5,%6,%7}, {%8,%9}, {%0,%1,%2,%3};"
        : "+f"(c[0]), "+f"(c[1]), "+f"(c[2]), "+f"(c[3])
        : "r"(a[0]), "r"(a[1]), "r"(a[2]), "r"(a[3]), "r"(b[0]), "r"(b[1]));
}

// ================= xsum: per-chunk partial column sums + zero g_T =================
__global__ __launch_bounds__(256) void xsum_kernel(const float* __restrict__ x) {
    __shared__ float4 red[4][64];
    int b = blockIdx.x >> 5, chunk = blockIdx.x & 31;
    int c4 = threadIdx.x & 63, rl = threadIdx.x >> 6;
    const float* base = x + ((size_t)b * NN + chunk * 256 + rl) * CC + c4 * 4;
    float4 s = make_float4(0.f, 0.f, 0.f, 0.f);
#pragma unroll 8
    for (int n = 0; n < 64; n++) {
        float4 v = *(const float4*)(base + (size_t)n * 4 * CC);
        s.x += v.x; s.y += v.y; s.z += v.z; s.w += v.w;
    }
    red[rl][c4] = s;
    for (int i = blockIdx.x * 256 + threadIdx.x; i < BB * KK * CC; i += 64 * 256)
        g_T[i] = 0.f;
    __syncthreads();
    if (rl == 0) {
        float4 a = red[0][c4], b2 = red[1][c4], c2 = red[2][c4], d = red[3][c4];
        float4 o;
        o.x = a.x + b2.x + c2.x + d.x; o.y = a.y + b2.y + c2.y + d.y;
        o.z = a.z + b2.z + c2.z + d.z; o.w = a.w + b2.w + c2.w + d.w;
        *(float4*)&g_part[(size_t)(b * 32 + chunk) * CC + c4 * 4] = o;
    }
}

// qsum = Wq*xsum + N*bq (fp32 exact), then u = Wk^T * qsum
__global__ void prep_kernel(const float* __restrict__ Wq, const float* __restrict__ bq,
                            const float* __restrict__ Wk) {
    __shared__ float xs[CC], qs[CC];
    int b = blockIdx.x, tid = threadIdx.x, w = tid >> 5, lane = tid & 31;
    float sx = 0.f;
#pragma unroll 8
    for (int ch = 0; ch < 32; ch++) sx += g_part[(size_t)(b * 32 + ch) * CC + tid];
    xs[tid] = sx;
    __syncthreads();
    for (int c = w * 32; c < w * 32 + 32; c++) {
        const float* wr = Wq + (size_t)c * CC;
        float s = 0.f;
#pragma unroll
        for (int i = 0; i < 8; i++) s += xs[lane + 32 * i] * wr[lane + 32 * i];
#pragma unroll
        for (int o = 16; o; o >>= 1) s += __shfl_xor_sync(0xFFFFFFFFu, s, o);
        if (lane == 0) qs[c] = s + (float)NN * bq[c];
    }
    __syncthreads();
    int c = tid;
    float u = 0.f;
#pragma unroll 8
    for (int d = 0; d < CC; d++) u += qs[d] * Wk[(size_t)d * CC + c];
    g_u[b * CC + c] = u;
}

// score_m = u_b . x_m  (order-identical to qsum.k_m/16 up to constant; exact fp32)
__global__ void score_kernel(const float* __restrict__ x) {
    int warp = threadIdx.x >> 5, lane = threadIdx.x & 31;
    int row = blockIdx.x * 8 + warp;
    int b = row >> 13;
    const float4* xr = (const float4*)(x + (size_t)row * CC);
    const float4* u = (const float4*)(&g_u[b * CC]);
    float4 v0 = xr[lane], v1 = xr[lane + 32];
    float4 u0 = u[lane], u1 = u[lane + 32];
    float s = v0.x * u0.x + v0.y * u0.y + v0.z * u0.z + v0.w * u0.w
            + v1.x * u1.x + v1.y * u1.y + v1.z * u1.z + v1.w * u1.w;
#pragma unroll
    for (int o = 16; o; o >>= 1) s += __shfl_xor_sync(0xFFFFFFFFu, s, o);
    if (lane == 0) g_score[row] = s;
}

// ================= exact top-40 via radix-256 select (one CTA per batch) =================
__global__ __launch_bounds__(1024) void topk_kernel() {
    __shared__ uint32_t su[NN];
    __shared__ int hist[256];
    __shared__ int c_hi_sh, bin_sh, cnt, chunk_tot, eq_cnt;
    __shared__ int wcnt[32], wpre[32];
    const int b = blockIdx.x, tid = threadIdx.x, lane = tid & 31, wid = tid >> 5;

    for (int i = tid; i < NN; i += 1024) {
        uint32_t u = __float_as_uint(g_score[b * NN + i]);
        su[i] = (u & 0x80000000u) ? ~u : (u | 0x80000000u);
    }
    if (tid == 0) { cnt = 0; eq_cnt = 0; }

    uint32_t prefix = 0;
    int K_rem = KK;
#pragma unroll
    for (int shift = 24; shift >= 0; shift -= 8) {
        __syncthreads();
        if (tid < 256) hist[tid] = 0;
        __syncthreads();
        const uint32_t mask_hi = (shift == 24) ? 0u : (0xFFFFFFFFu << (shift + 8));
#pragma unroll
        for (int c = 0; c < NN / 1024; c++) {
            uint32_t u = su[c * 1024 + tid];
            int bin = ((u & mask_hi) == prefix) ? (int)((u >> shift) & 0xFF) : 256;
            uint32_t grp = __match_any_sync(0xFFFFFFFFu, bin);
            if (bin < 256 && (__ffs(grp) - 1) == lane) atomicAdd(&hist[bin], __popc(grp));
        }
        __syncthreads();
        if (wid == 0) {
            int h[8], lsum = 0;
#pragma unroll
            for (int j = 0; j < 8; j++) { h[j] = hist[lane * 8 + j]; lsum += h[j]; }
            int acc = lsum;
#pragma unroll
            for (int off = 1; off < 32; off <<= 1) {
                int v = __shfl_down_sync(0xFFFFFFFFu, acc, off);
                if (lane + off < 32) acc += v;
            }
            int run = acc - lsum;
#pragma unroll
            for (int j = 7; j >= 0; j--) {
                int above = run;
                if (above < K_rem && above + h[j] >= K_rem) {
                    bin_sh = lane * 8 + j;
                    c_hi_sh = above;
                }
                run += h[j];
            }
        }
        __syncthreads();
        K_rem -= c_hi_sh;
        prefix |= ((uint32_t)bin_sh) << shift;
    }
    __syncthreads();

    const uint32_t u_thr = prefix;
    int myeq = 0;
#pragma unroll
    for (int c = 0; c < NN / 1024; c++) myeq += (su[c * 1024 + tid] == u_thr);
#pragma unroll
    for (int o = 16; o; o >>= 1) myeq += __shfl_xor_sync(0xFFFFFFFFu, myeq, o);
    if (lane == 0 && myeq) atomicAdd(&eq_cnt, myeq);
    __syncthreads();

    if (eq_cnt == K_rem) {
#pragma unroll
        for (int c = 0; c < NN / 1024; c++) {
            const int i = c * 1024 + tid;
            if (su[i] >= u_thr) {
                int slot = atomicAdd(&cnt, 1);
                g_selidx[b * KK + slot] = i;
            }
        }
    } else {
        int running = 0;
#pragma unroll
        for (int c = 0; c < NN / 1024; c++) {
            const int i = c * 1024 + tid;
            const uint32_t u = su[i];
            const bool eq = (u == u_thr);
            if (u > u_thr) {
                int slot = atomicAdd(&cnt, 1);
                g_selidx[b * KK + slot] = i;
            }
            uint32_t bal = __ballot_sync(0xFFFFFFFFu, eq);
            if (lane == 0) wcnt[wid] = __popc(bal);
            __syncthreads();
            if (wid == 0) {
                int v = wcnt[lane], p = v;
#pragma unroll
                for (int off = 1; off < 32; off <<= 1) {
                    int t = __shfl_up_sync(0xFFFFFFFFu, p, off);
                    if (lane >= off) p += t;
                }
                wpre[lane] = p - v;
                if (lane == 31) chunk_tot = p;
            }
            __syncthreads();
            if (eq) {
                int r = running + wpre[wid] + __popc(bal & ((1u << lane) - 1u));
                if (r < K_rem) {
                    int slot = atomicAdd(&cnt, 1);
                    g_selidx[b * KK + slot] = i;
                }
            }
            running += chunk_tot;
            __syncthreads();
        }
    }
}

// ================= fp16 mma GEMM: out[m,n] = X[m,:].W[n,:] + bias[n] =================
#define GA0 0u
#define GA1 2560u
#define GB0 5120u
#define GB1 7680u
#define G_SMEM (10240u * 4u)

__global__ __launch_bounds__(256) void gemm_mma(
    const float* __restrict__ X,
    const float* __restrict__ W0, const float* __restrict__ W1, const float* __restrict__ W2,
    const float* __restrict__ B0, const float* __restrict__ B1, const float* __restrict__ B2,
    float* __restrict__ O0, float* __restrict__ O1, float* __restrict__ O2) {
    extern __shared__ __align__(16) uint32_t sm[];
    const int z = blockIdx.z;
    const float* W = (z == 0) ? W0 : (z == 1) ? W1 : W2;
    const float* bias = (z == 0) ? B0 : (z == 1) ? B1 : B2;
    float* out = (z == 0) ? O0 : (z == 1) ? O1 : O2;

    const int tid = threadIdx.x, lane = tid & 31, wid = tid >> 5;
    const int m0 = blockIdx.x * 128;
    const int n0 = blockIdx.y * 128;
    const int wm = wid & 1, wn = wid >> 1;

    float c[4][4][4];
#pragma unroll
    for (int mf = 0; mf < 4; mf++)
#pragma unroll
        for (int nf = 0; nf < 4; nf++)
#pragma unroll
            for (int j = 0; j < 4; j++) c[mf][nf][j] = 0.f;

    float4 av[4], bv[4];
#pragma unroll
    for (int i = 0; i < 4; i++) {
        int idx = tid + i * 256;
        int r = idx >> 3, c4 = idx & 7;
        av[i] = *(const float4*)(X + (size_t)(m0 + r) * CC + c4 * 4);
        bv[i] = *(const float4*)(W + (size_t)(n0 + r) * CC + c4 * 4);
    }
#pragma unroll
    for (int i = 0; i < 4; i++) {
        int idx = tid + i * 256;
        int r = idx >> 3, c4 = idx & 7;
        uint2 ha = make_uint2(pk2(av[i].x, av[i].y), pk2(av[i].z, av[i].w));
        uint2 hb = make_uint2(pk2(bv[i].x, bv[i].y), pk2(bv[i].z, bv[i].w));
        *(uint2*)&sm[GA0 + r * 20 + c4 * 2] = ha;
        *(uint2*)&sm[GB0 + r * 20 + c4 * 2] = hb;
    }
    __syncthreads();

    for (int ch = 0; ch < 8; ch++) {
        if (ch < 7) {
            int k0 = (ch + 1) * 32;
#pragma unroll
            for (int i = 0; i < 4; i++) {
                int idx = tid + i * 256;
                int r = idx >> 3, c4 = idx & 7;
                av[i] = *(const float4*)(X + (size_t)(m0 + r) * CC + k0 + c4 * 4);
                bv[i] = *(const float4*)(W + (size_t)(n0 + r) * CC + k0 + c4 * 4);
            }
        }
        const uint32_t Ab = (ch & 1) ? GA1 : GA0;
        const uint32_t Bb = (ch & 1) ? GB1 : GB0;
#pragma unroll
        for (int s = 0; s < 2; s++) {
            const uint32_t abase = Ab + (wm * 64 + (lane >> 2)) * 20 + (lane & 3) + s * 8;
            const uint32_t bbase = Bb + (wn * 32 + (lane >> 2)) * 20 + (lane & 3) + s * 8;
            uint32_t a[4][4], b[4][2];
#pragma unroll
            for (int mf = 0; mf < 4; mf++) {
                a[mf][0] = sm[abase + mf * 320];
                a[mf][1] = sm[abase + mf * 320 + 160];
                a[mf][2] = sm[abase + mf * 320 + 4];
                a[mf][3] = sm[abase + mf * 320 + 164];
            }
#pragma unroll
            for (int nf = 0; nf < 4; nf++) {
                b[nf][0] = sm[bbase + nf * 160];
                b[nf][1] = sm[bbase + nf * 160 + 4];
            }
#pragma unroll
            for (int mf = 0; mf < 4; mf++)
#pragma unroll
                for (int nf = 0; nf < 4; nf++) mma16(c[mf][nf], a[mf], b[nf]);
        }
        if (ch < 7) {
            const uint32_t An = (ch & 1) ? GA0 : GA1;
            const uint32_t Bn = (ch & 1) ? GB0 : GB1;
#pragma unroll
            for (int i = 0; i < 4; i++) {
                int idx = tid + i * 256;
                int r = idx >> 3, c4 = idx & 7;
                uint2 ha = make_uint2(pk2(av[i].x, av[i].y), pk2(av[i].z, av[i].w));
                uint2 hb = make_uint2(pk2(bv[i].x, bv[i].y), pk2(bv[i].z, bv[i].w));
                *(uint2*)&sm[An + r * 20 + c4 * 2] = ha;
                *(uint2*)&sm[Bn + r * 20 + c4 * 2] = hb;
            }
            __syncthreads();
        }
    }

#pragma unroll
    for (int nf = 0; nf < 4; nf++) {
        const int col = n0 + wn * 32 + nf * 8 + 2 * (lane & 3);
        const float bi0 = bias[col], bi1 = bias[col + 1];
#pragma unroll
        for (int mf = 0; mf < 4; mf++) {
            const int row = m0 + wm * 64 + mf * 16 + (lane >> 2);
            size_t o0 = (size_t)row * CC + col;
            size_t o1 = (size_t)(row + 8) * CC + col;
            float2 v0, v1;
            v0.x = c[mf][nf][0] + bi0; v0.y = c[mf][nf][1] + bi1;
            v1.x = c[mf][nf][2] + bi0; v1.y = c[mf][nf][3] + bi1;
            *(float2*)(out + o0) = v0;
            *(float2*)(out + o1) = v1;
        }
    }
}

// ================= landmark softmax via fp16 mma (+fused T-accumulate on k side) =================
// side=0: q -> Pq to gmem.  side=1: k -> P in smem, T accumulated (no gmem P).
#define LSEL 0u
#define LA0 5280u
#define LA1 7840u
#define L_SMEM (10400u * 4u)

__global__ __launch_bounds__(256) void lm_mma(int side) {
    extern __shared__ __align__(16) uint32_t sm[];
    const int tid = threadIdx.x, lane = tid & 31, wid = tid >> 5;
    const int m0 = blockIdx.x * 128;
    const int b = m0 >> 13;
    const float* src = side ? g_k : g_q;

#pragma unroll
    for (int i = 0; i < 10; i++) {
        int idx = tid + i * 256;
        int r = idx >> 6, c4 = idx & 63;
        const float* rp = g_k + ((size_t)b * NN + g_selidx[b * KK + r]) * CC;
        float4 v = *(const float4*)(rp + c4 * 4);
        uint2 h = make_uint2(pk2(v.x, v.y), pk2(v.z, v.w));
        *(uint2*)&sm[LSEL + r * 132 + c4 * 2] = h;
    }
    float4 av[4];
#pragma unroll
    for (int i = 0; i < 4; i++) {
        int idx = tid + i * 256;
        int r = idx >> 3, c4 = idx & 7;
        av[i] = *(const float4*)(src + (size_t)(m0 + r) * CC + c4 * 4);
    }
#pragma unroll
    for (int i = 0; i < 4; i++) {
        int idx = tid + i * 256;
        int r = idx >> 3, c4 = idx & 7;
        uint2 ha = make_uint2(pk2(av[i].x, av[i].y), pk2(av[i].z, av[i].w));
        *(uint2*)&sm[LA0 + r * 20 + c4 * 2] = ha;
    }
    __syncthreads();

    float c[5][4];
#pragma unroll
    for (int nf = 0; nf < 5; nf++)
#pragma unroll
        for (int j = 0; j < 4; j++) c[nf][j] = 0.f;

    for (int ch = 0; ch < 8; ch++) {
        if (ch < 7) {
            int k0 = (ch + 1) * 32;
#pragma unroll
            for (int i = 0; i < 4; i++) {
                int idx = tid + i * 256;
                int r = idx >> 3, c4 = idx & 7;
                av[i] = *(const float4*)(src + (size_t)(m0 + r) * CC + k0 + c4 * 4);
            }
        }
        const uint32_t Ab = (ch & 1) ? LA1 : LA0;
#pragma unroll
        for (int s = 0; s < 2; s++) {
            const uint32_t abase = Ab + (wid * 16 + (lane >> 2)) * 20 + (lane & 3) + s * 8;
            const uint32_t sbase = LSEL + (lane >> 2) * 132 + (lane & 3) + ch * 16 + s * 8;
            uint32_t a[4], bfr[5][2];
            a[0] = sm[abase];
            a[1] = sm[abase + 160];
            a[2] = sm[abase + 4];
            a[3] = sm[abase + 164];
#pragma unroll
            for (int nf = 0; nf < 5; nf++) {
                bfr[nf][0] = sm[sbase + nf * 8 * 132];
                bfr[nf][1] = sm[sbase + nf * 8 * 132 + 4];
            }
#pragma unroll
            for (int nf = 0; nf < 5; nf++) mma16(c[nf], a, bfr[nf]);
        }
        if (ch < 7) {
            const uint32_t An = (ch & 1) ? LA0 : LA1;
#pragma unroll
            for (int i = 0; i < 4; i++) {
                int idx = tid + i * 256;
                int r = idx >> 3, c4 = idx & 7;
                uint2 ha = make_uint2(pk2(av[i].x, av[i].y), pk2(av[i].z, av[i].w));
                *(uint2*)&sm[An + r * 20 + c4 * 2] = ha;
            }
            __syncthreads();
        }
    }

    float v0[10], v1[10];
#pragma unroll
    for (int nf = 0; nf < 5; nf++) {
        v0[nf * 2] = c[nf][0]; v0[nf * 2 + 1] = c[nf][1];
        v1[nf * 2] = c[nf][2]; v1[nf * 2 + 1] = c[nf][3];
    }
    float mx0 = v0[0], mx1 = v1[0];
#pragma unroll
    for (int i = 1; i < 10; i++) { mx0 = fmaxf(mx0, v0[i]); mx1 = fmaxf(mx1, v1[i]); }
    mx0 = fmaxf(mx0, __shfl_xor_sync(0xFFFFFFFFu, mx0, 1));
    mx0 = fmaxf(mx0, __shfl_xor_sync(0xFFFFFFFFu, mx0, 2));
    mx1 = fmaxf(mx1, __shfl_xor_sync(0xFFFFFFFFu, mx1, 1));
    mx1 = fmaxf(mx1, __shfl_xor_sync(0xFFFFFFFFu, mx1, 2));
    float s0 = 0.f, s1 = 0.f;
#pragma unroll
    for (int i = 0; i < 10; i++) {
        v0[i] = __expf((v0[i] - mx0) * 0.0625f); s0 += v0[i];
        v1[i] = __expf((v1[i] - mx1) * 0.0625f); s1 += v1[i];
    }
    s0 += __shfl_xor_sync(0xFFFFFFFFu, s0, 1);
    s0 += __shfl_xor_sync(0xFFFFFFFFu, s0, 2);
    s1 += __shfl_xor_sync(0xFFFFFFFFu, s1, 1);
    s1 += __shfl_xor_sync(0xFFFFFFFFu, s1, 2);
    const float i0 = 1.f / s0, i1 = 1.f / s1;
    const int lr0 = wid * 16 + (lane >> 2);

    if (side == 0) {
#pragma unroll
        for (int nf = 0; nf < 5; nf++) {
            int col = nf * 8 + 2 * (lane & 3);
            float2 w0, w1;
            w0.x = v0[nf * 2] * i0; w0.y = v0[nf * 2 + 1] * i0;
            w1.x = v1[nf * 2] * i1; w1.y = v1[nf * 2 + 1] * i1;
            *(float2*)&g_Pq[(size_t)(m0 + lr0) * KK + col] = w0;
            *(float2*)&g_Pq[(size_t)(m0 + lr0 + 8) * KK + col] = w1;
        }
    } else {
        __syncthreads();
        float* Psh = (float*)&sm[LA0];
#pragma unroll
        for (int nf = 0; nf < 5; nf++) {
            int col = nf * 8 + 2 * (lane & 3);
            Psh[lr0 * KK + col] = v0[nf * 2] * i0;
            Psh[lr0 * KK + col + 1] = v0[nf * 2 + 1] * i0;
            Psh[(lr0 + 8) * KK + col] = v1[nf * 2] * i1;
            Psh[(lr0 + 8) * KK + col + 1] = v1[nf * 2 + 1] * i1;
        }
        __syncthreads();
        const int cc = tid;
        float acc[KK];
#pragma unroll
        for (int j = 0; j < KK; j++) acc[j] = 0.f;
        const float* v = &g_v[(size_t)m0 * CC + cc];
        for (int n = 0; n < 128; n++) {
            float val = v[(size_t)n * CC];
            const float* pr = &Psh[n * KK];
#pragma unroll
            for (int j = 0; j < KK; j += 4) {
                float4 p = *(const float4*)&pr[j];
                acc[j + 0] += p.x * val; acc[j + 1] += p.y * val;
                acc[j + 2] += p.z * val; acc[j + 3] += p.w * val;
            }
        }
        float* T = &g_T[(size_t)b * KK * CC + cc];
#pragma unroll
        for (int j = 0; j < KK; j++) atomicAdd(&T[j * CC], acc[j]);
    }
}

// ================= T2 = T @ Wo^T  (warp-per-column, coalesced Wo loads) =================
__global__ __launch_bounds__(256) void t2_kernel(const float* __restrict__ Wo) {
    __shared__ float t[CC];
    const int b = blockIdx.x / KK, j = blockIdx.x % KK;
    const int tid = threadIdx.x, lane = tid & 31, wid = tid >> 5;
    t[tid] = g_T[((size_t)b * KK + j) * CC + tid];
    __syncthreads();
    const float4* ts = (const float4*)t;
    for (int c = wid; c < CC; c += 8) {
        const float4* w4 = (const float4*)(Wo + (size_t)c * CC);
        float4 wa = w4[lane], wb = w4[lane + 32];
        float4 ta = ts[lane], tb = ts[lane + 32];
        float s = wa.x * ta.x + wa.y * ta.y + wa.z * ta.z + wa.w * ta.w
                + wb.x * tb.x + wb.y * tb.y + wb.z * tb.z + wb.w * tb.w;
#pragma unroll
        for (int o = 16; o; o >>= 1) s += __shfl_xor_sync(0xFFFFFFFFu, s, o);
        if (lane == 0) g_T2[((size_t)b * KK + j) * CC + c] = s;
    }
}

// ================= final output: out = Pq @ T2 + bo + query (32 rows/CTA, 512 CTAs) =================
__global__ __launch_bounds__(256) void out_kernel(const float* __restrict__ query,
                                                  const float* __restrict__ bo,
                                                  float* __restrict__ out) {
    __shared__ float P_sh[32 * KK];
    int b = blockIdx.y;
    int n0 = blockIdx.x * 32;
    int c = threadIdx.x;
    const float* Pg = &g_Pq[((size_t)b * NN + n0) * KK];
#pragma unroll
    for (int i = c * 4; i < 32 * KK; i += 1024)
        *(float4*)&P_sh[i] = *(const float4*)&Pg[i];
    float t[KK];
    const float* T2 = &g_T2[(size_t)b * KK * CC + c];
#pragma unroll
    for (int j = 0; j < KK; j++) t[j] = T2[j * CC];
    const float bias = bo[c];
    __syncthreads();
    const float* q = query + ((size_t)b * NN + n0) * CC + c;
    float* o = out + ((size_t)b * NN + n0) * CC + c;
#pragma unroll
    for (int nb = 0; nb < 32; nb += 8) {
        float qv[8];
#pragma unroll
        for (int m = 0; m < 8; m++) qv[m] = q[(size_t)(nb + m) * CC];   // 8 outstanding loads
#pragma unroll
        for (int m = 0; m < 8; m++) {
            const float* pr = &P_sh[(nb + m) * KK];
            float s = 0.f;
#pragma unroll
            for (int j = 0; j < KK; j += 4) {
                float4 p = *(const float4*)&pr[j];
                s += p.x * t[j + 0] + p.y * t[j + 1] + p.z * t[j + 2] + p.w * t[j + 3];
            }
            o[(size_t)(nb + m) * CC] = s + bias + qv[m];
        }
    }
}

// ================= launch =================
extern "C" void kernel_launch(void* const* d_in, const int* in_sizes, int n_in,
                              void* d_out, int out_size) {
    (void)in_sizes; (void)n_in; (void)out_size;
    const float* query = (const float*)d_in[0];
    const float* Wq = (const float*)d_in[1];
    const float* bq = (const float*)d_in[2];
    const float* Wk = (const float*)d_in[3];
    const float* bk = (const float*)d_in[4];
    const float* Wv = (const float*)d_in[5];
    const float* bv = (const float*)d_in[6];
    const float* Wo = (const float*)d_in[7];
    const float* bo = (const float*)d_in[8];
    float* out = (float*)d_out;

    cudaFuncSetAttribute(gemm_mma, cudaFuncAttributeMaxDynamicSharedMemorySize, G_SMEM);
    cudaFuncSetAttribute(lm_mma, cudaFuncAttributeMaxDynamicSharedMemorySize, L_SMEM);

    float *p_q, *p_k, *p_v;
    cudaGetSymbolAddress((void**)&p_q, g_q);
    cudaGetSymbolAddress((void**)&p_k, g_k);
    cudaGetSymbolAddress((void**)&p_v, g_v);

    // Fork: small latency-bound selection chain overlaps the QKV GEMM.
    cudaStream_t s2;
    cudaEvent_t e1, e2, e_qkv, e4;
    cudaStreamCreateWithFlags(&s2, cudaStreamNonBlocking);
    cudaEventCreateWithFlags(&e1, cudaEventDisableTiming);
    cudaEventCreateWithFlags(&e2, cudaEventDisableTiming);
    cudaEventCreateWithFlags(&e_qkv, cudaEventDisableTiming);
    cudaEventCreateWithFlags(&e4, cudaEventDisableTiming);

    cudaEventRecord(e1, 0);
    cudaStreamWaitEvent(s2, e1, 0);

    // chain A on s2: landmark selection
    xsum_kernel<<<64, 256, 0, s2>>>(query);
    prep_kernel<<<BB, 256, 0, s2>>>(Wq, bq, Wk);
    score_kernel<<<MM / 8, 256, 0, s2>>>(query);
    topk_kernel<<<BB, 1024, 0, s2>>>();
    cudaEventRecord(e2, s2);

    // chain B on main: QKV projections
    dim3 gqkv(MM / 128, CC / 128, 3);
    gemm_mma<<<gqkv, 256, G_SMEM>>>(query, Wq, Wk, Wv, bq, bk, bv, p_q, p_k, p_v);
    cudaEventRecord(e_qkv, 0);

    // join selection into main; k-side landmark+T on main, q-side on s2 (concurrent)
    cudaStreamWaitEvent(0, e2, 0);
    cudaStreamWaitEvent(s2, e_qkv, 0);

    lm_mma<<<MM / 128, 256, L_SMEM, 0>>>(1);      // k side -> g_T
    lm_mma<<<MM / 128, 256, L_SMEM, s2>>>(0);     // q side -> g_Pq (overlaps)
    cudaEventRecord(e4, s2);

    t2_kernel<<<BB * KK, 256>>>(Wo);              // after k side (same stream)

    cudaStreamWaitEvent(0, e4, 0);                // need g_Pq too
    dim3 gt(NN / 32, BB);
    out_kernel<<<gt, 256>>>(query, bo, out);

    cudaStreamDestroy(s2);
    cudaEventDestroy(e1);
    cudaEventDestroy(e2);
    cudaEventDestroy(e_qkv);
    cudaEventDestroy(e4);
}